// round 5
// baseline (speedup 1.0000x reference)
#include <cuda_runtime.h>
#include <math_constants.h>

// Problem constants
constexpr int NB = 128, NK = 8, NV = 50257, NL = 64, NMAXL = 128, NA = 512, ND = 1024;
constexpr int NEOS = 2;
constexpr int ROWS = NB * NK;   // 1024

// Output layout (single float32 dtype; integer outputs written as floats)
constexpr size_t OFF0 = 0;
constexpr size_t OFF1 = OFF0 + (size_t)NB * NK;
constexpr size_t OFF2 = OFF1 + (size_t)NB * NK * (NL + 1);
constexpr size_t OFF3 = OFF2 + (size_t)NB * NK;
constexpr size_t OFF4 = OFF3 + (size_t)NB * NK;
constexpr size_t OFF5 = OFF4 + (size_t)NB * NK * NMAXL;
constexpr size_t OFF6 = OFF5 + (size_t)NB * NK;
constexpr size_t OFF7 = OFF6 + (size_t)NB * NK * NA;
constexpr size_t OFF8 = OFF7 + (size_t)NB * NK * ND;

// Device scratch
__device__ float g_top_val[ROWS * 8];
__device__ int   g_top_idx[ROWS * 8];
__device__ float g_row_c[ROWS];
__device__ float g_eos[ROWS];

// Packed orderable key: larger == (larger val, then smaller idx). 0 = sentinel.
__device__ __forceinline__ unsigned long long pack_key(float v, unsigned int idx) {
    unsigned int u = __float_as_uint(v);
    u = (u & 0x80000000u) ? ~u : (u | 0x80000000u);
    return ((unsigned long long)u << 32) | (unsigned long long)(0xFFFFFFFFu - idx);
}
__device__ __forceinline__ float key_val(unsigned long long k) {
    unsigned int u = (unsigned int)(k >> 32);
    unsigned int bits = (u & 0x80000000u) ? (u ^ 0x80000000u) : ~u;
    return __uint_as_float(bits);
}
__device__ __forceinline__ int key_idx(unsigned long long k) {
    return (int)(0xFFFFFFFFu - (unsigned int)(k & 0xFFFFFFFFu));
}

constexpr int CAP = 4096;

struct RedSmem {
    unsigned long long keys[16];
    unsigned long long win;
};

// Block-wide argmax over packed keys (512 threads). All threads must call.
__device__ __forceinline__ unsigned long long block_argmax(unsigned long long my,
                                                           RedSmem& rs, int tid) {
    int lane = tid & 31, wid = tid >> 5;
    unsigned long long k = my;
#pragma unroll
    for (int off = 16; off; off >>= 1) {
        unsigned long long o = __shfl_xor_sync(0xFFFFFFFFu, k, off);
        if (o > k) k = o;
    }
    if (lane == 0) rs.keys[wid] = k;
    __syncthreads();
    if (tid < 16) {
        unsigned long long kk = rs.keys[tid];
#pragma unroll
        for (int off = 8; off; off >>= 1) {
            unsigned long long o = __shfl_xor_sync(0x0000FFFFu, kk, off);
            if (o > kk) kk = o;
        }
        if (tid == 0) rs.win = kk;
    }
    __syncthreads();
    return rs.win;
}

// ---------------------------------------------------------------------------
// Kernel 1: per (b,k) row — fused sumexp + threshold-filtered top-8
// ---------------------------------------------------------------------------
__global__ __launch_bounds__(512) void k_rows(const float* __restrict__ logits,
                                              const float* __restrict__ cand_scores) {
    const int row = blockIdx.x;
    const int tid = threadIdx.x;
    const float* rl = logits + (long long)row * NV;

    __shared__ unsigned long long s_buf[CAP];
    __shared__ float s_red[512];
    __shared__ RedSmem s_rs;
    __shared__ int s_cnt;
    __shared__ float s_eosv;
    __shared__ float s_tau;

    if (tid == 0) s_cnt = 0;

    // ---- Phase 1: tau = 8th largest of first 1024 elements (EOS excluded) ----
    {
        float x0 = rl[tid];
        float x1 = rl[tid + 512];
        if (tid == NEOS) s_eosv = x0;
        unsigned long long k0 = (tid == NEOS) ? 0ULL : pack_key(x0, (unsigned)tid);
        unsigned long long k1 = pack_key(x1, (unsigned)(tid + 512));
        unsigned long long win = 0;
        for (int r = 0; r < 8; ++r) {
            unsigned long long my = (k0 > k1) ? k0 : k1;
            win = block_argmax(my, s_rs, tid);
            if (k0 == win) k0 = 0;
            if (k1 == win) k1 = 0;
        }
        if (tid == 0) s_tau = key_val(win);
        __syncthreads();
    }
    const float tau = s_tau;

    // ---- Phase 2: full scan: sumexp + push candidates (x >= tau; EOS filtered later)
    float sum0 = 0.f, sum1 = 0.f, sum2 = 0.f, sum3 = 0.f;

    // alignment peel (row base is only 4B aligned)
    const int pre = (int)(((16u - ((unsigned)(unsigned long long)rl & 15u)) & 15u) >> 2);
    const int nvec = (NV - pre) >> 2;
    const int tstart = pre + nvec * 4;

    {
        bool act = tid < pre;
        float x = act ? rl[tid] : -CUDART_INF_F;
        sum0 += __expf(x);
        if (__any_sync(0xFFFFFFFFu, x >= tau)) {
            if (x >= tau) {
                int p = atomicAdd(&s_cnt, 1);
                if (p < CAP) s_buf[p] = pack_key(x, (unsigned)tid);
            }
        }
    }

    // Warp-uniform trip count: EVERY thread runs niter iterations so the
    // __any_sync collectives inside are always executed by full warps.
    const float4* rl4 = (const float4*)(rl + pre);
    const int niter = (nvec + 511) >> 9;
#pragma unroll 4
    for (int it = 0; it < niter; ++it) {
        int v = tid + (it << 9);
        bool act = v < nvec;
        float4 q = make_float4(-CUDART_INF_F, -CUDART_INF_F, -CUDART_INF_F, -CUDART_INF_F);
        if (act) q = rl4[v];
        sum0 += __expf(q.x);
        sum1 += __expf(q.y);
        sum2 += __expf(q.z);
        sum3 += __expf(q.w);
        if (__any_sync(0xFFFFFFFFu, q.x >= tau)) {
            if (q.x >= tau) {
                int p = atomicAdd(&s_cnt, 1);
                if (p < CAP) s_buf[p] = pack_key(q.x, (unsigned)(pre + 4 * v + 0));
            }
        }
        if (__any_sync(0xFFFFFFFFu, q.y >= tau)) {
            if (q.y >= tau) {
                int p = atomicAdd(&s_cnt, 1);
                if (p < CAP) s_buf[p] = pack_key(q.y, (unsigned)(pre + 4 * v + 1));
            }
        }
        if (__any_sync(0xFFFFFFFFu, q.z >= tau)) {
            if (q.z >= tau) {
                int p = atomicAdd(&s_cnt, 1);
                if (p < CAP) s_buf[p] = pack_key(q.z, (unsigned)(pre + 4 * v + 2));
            }
        }
        if (__any_sync(0xFFFFFFFFu, q.w >= tau)) {
            if (q.w >= tau) {
                int p = atomicAdd(&s_cnt, 1);
                if (p < CAP) s_buf[p] = pack_key(q.w, (unsigned)(pre + 4 * v + 3));
            }
        }
    }

    {
        bool act = tid < NV - tstart;
        int idx = tstart + tid;
        float x = act ? rl[idx] : -CUDART_INF_F;
        sum0 += __expf(x);
        if (__any_sync(0xFFFFFFFFu, x >= tau)) {
            if (x >= tau) {
                int p = atomicAdd(&s_cnt, 1);
                if (p < CAP) s_buf[p] = pack_key(x, (unsigned)idx);
            }
        }
    }

    // ---- Sum reduce -> logZ ----
    s_red[tid] = (sum0 + sum1) + (sum2 + sum3);
    __syncthreads();
#pragma unroll
    for (int s = 256; s > 0; s >>= 1) {
        if (tid < s) s_red[tid] += s_red[tid + s];
        __syncthreads();
    }
    float logZ = logf(s_red[0]);

    if (tid == 0) {
        float cs = cand_scores[row];
        g_row_c[row] = cs - logZ;
        g_eos[row]   = s_eosv - logZ + cs;
    }

    const int cnt = s_cnt;
    if (cnt <= CAP) {
        // remove EOS entry if it slipped in (tau guarantees >=8 non-EOS survivors)
        for (int i = tid; i < cnt; i += 512)
            if (key_idx(s_buf[i]) == NEOS) s_buf[i] = 0;
        __syncthreads();
        // ---- Top-8 from candidate buffer: 8 block-argmax rounds ----
        for (int r = 0; r < 8; ++r) {
            unsigned long long my = 0;
            for (int i = tid; i < cnt; i += 512) {
                unsigned long long k = s_buf[i];
                if (k > my) my = k;
            }
            unsigned long long win = block_argmax(my, s_rs, tid);
            if (tid == 0) {
                g_top_val[row * 8 + r] = key_val(win);
                g_top_idx[row * 8 + r] = key_idx(win);
            }
            for (int i = tid; i < cnt; i += 512) {
                if (s_buf[i] == win) s_buf[i] = 0;
            }
            __syncthreads();
        }
    } else {
        // ---- Correct fallback (statistically never taken): per-thread sorted top-8 ----
        float tv[8]; int ti[8];
#pragma unroll
        for (int j = 0; j < 8; j++) { tv[j] = -CUDART_INF_F; ti[j] = 0x7FFFFFFF; }
        for (int v = tid; v < NV; v += 512) {
            if (v == NEOS) continue;
            float x = rl[v];
            if ((x > tv[7]) || (x == tv[7] && v < ti[7])) {
                tv[7] = x; ti[7] = v;
#pragma unroll
                for (int j = 7; j >= 1; --j) {
                    bool sw = (tv[j] > tv[j-1]) || (tv[j] == tv[j-1] && ti[j] < ti[j-1]);
                    float av = sw ? tv[j] : tv[j-1];
                    float bv = sw ? tv[j-1] : tv[j];
                    int ai = sw ? ti[j] : ti[j-1];
                    int bi = sw ? ti[j-1] : ti[j];
                    tv[j-1] = av; ti[j-1] = ai; tv[j] = bv; ti[j] = bi;
                }
            }
        }
        for (int r = 0; r < 8; ++r) {
            unsigned long long my = pack_key(tv[0], (unsigned)ti[0]);
            unsigned long long win = block_argmax(my, s_rs, tid);
            if (tid == 0) {
                g_top_val[row * 8 + r] = key_val(win);
                g_top_idx[row * 8 + r] = key_idx(win);
            }
            if (my == win) {
#pragma unroll
                for (int j = 0; j < 7; j++) { tv[j] = tv[j+1]; ti[j] = ti[j+1]; }
                tv[7] = -CUDART_INF_F; ti[7] = 0x7FFFFFFF;
            }
            __syncthreads();
        }
    }
}

// ---------------------------------------------------------------------------
// Kernel 2 (fused): per-batch merge + completed top-k + seq writes + gathers
// ---------------------------------------------------------------------------
__global__ __launch_bounds__(512) void k_epilogue(const int* __restrict__ cand_seqs,
                                                  const float* __restrict__ completed_scores,
                                                  const int* __restrict__ completed_seqs,
                                                  const int* __restrict__ completed_length,
                                                  const float* __restrict__ dctx,
                                                  const float* __restrict__ dr1,
                                                  const float* __restrict__ dr2,
                                                  float* __restrict__ out) {
    int b = blockIdx.x, t = threadIdx.x;
    __shared__ float s_cv[64]; __shared__ int s_ci[64];
    __shared__ float s_selval[8]; __shared__ int s_selpar[8]; __shared__ int s_selsym[8];
    __shared__ float s_cscore[8]; __shared__ int s_clen[8]; __shared__ int s_cidx[8];

    if (t < 64) {
        int k = t >> 3;
        s_cv[t] = g_top_val[(b * 8 + k) * 8 + (t & 7)] + g_row_c[b * 8 + k];
        s_ci[t] = g_top_idx[(b * 8 + k) * 8 + (t & 7)];
    }
    __syncthreads();

    if (t == 0) {
        float bv[8]; long long bf[8]; int bp[8]; int bs[8];
#pragma unroll
        for (int j = 0; j < 8; j++) { bv[j] = -CUDART_INF_F; bf[j] = 0x7FFFFFFFFFFFFFFFLL; bp[j] = 0; bs[j] = 0; }
        for (int j = 0; j < 64; j++) {
            float x = s_cv[j]; int par = j >> 3; int sym = s_ci[j];
            long long fl = (long long)par * NV + sym;
            if (x > bv[7] || (x == bv[7] && fl < bf[7])) {
                bv[7] = x; bf[7] = fl; bp[7] = par; bs[7] = sym;
#pragma unroll
                for (int q = 7; q >= 1; --q) {
                    bool sw = (bv[q] > bv[q-1]) || (bv[q] == bv[q-1] && bf[q] < bf[q-1]);
                    if (sw) {
                        float tf = bv[q]; bv[q] = bv[q-1]; bv[q-1] = tf;
                        long long tl = bf[q]; bf[q] = bf[q-1]; bf[q-1] = tl;
                        int tp = bp[q]; bp[q] = bp[q-1]; bp[q-1] = tp;
                        int ts = bs[q]; bs[q] = bs[q-1]; bs[q-1] = ts;
                    }
                }
            }
        }
#pragma unroll
        for (int j = 0; j < 8; j++) {
            s_selval[j] = bv[j]; s_selpar[j] = bp[j]; s_selsym[j] = bs[j];
        }
    } else if (t == 32) {
        float cs[16]; int cl[16];
        for (int k = 0; k < 8; k++) { cs[k] = completed_scores[b * 8 + k]; cl[k] = completed_length[b * 8 + k]; }
        for (int k = 0; k < 8; k++) { cs[8 + k] = g_eos[b * 8 + k]; cl[8 + k] = NL + 1; }
        float bv[8]; int bi[8];
#pragma unroll
        for (int j = 0; j < 8; j++) { bv[j] = -CUDART_INF_F; bi[j] = 0x7FFFFFFF; }
        for (int j = 0; j < 16; j++) {
            float r = cs[j] / (float)cl[j];
            if (r > bv[7] || (r == bv[7] && j < bi[7])) {
                bv[7] = r; bi[7] = j;
#pragma unroll
                for (int q = 7; q >= 1; --q) {
                    bool sw = (bv[q] > bv[q-1]) || (bv[q] == bv[q-1] && bi[q] < bi[q-1]);
                    if (sw) {
                        float tf = bv[q]; bv[q] = bv[q-1]; bv[q-1] = tf;
                        int tq = bi[q]; bi[q] = bi[q-1]; bi[q-1] = tq;
                    }
                }
            }
        }
        for (int j = 0; j < 8; j++) {
            int ci = bi[j];
            s_cidx[j] = ci; s_cscore[j] = cs[ci]; s_clen[j] = cl[ci];
        }
    }
    __syncthreads();

    float* o_scores = out + OFF0;
    float* o_seqs   = out + OFF1;
    float* o_par    = out + OFF2;
    float* o_cscore = out + OFF3;
    float* o_cseqs  = out + OFF4;
    float* o_clen   = out + OFF5;

    if (t < 8) {
        o_scores[b * 8 + t] = s_selval[t];
        o_par[b * 8 + t]    = (float)s_selpar[t];
        o_cscore[b * 8 + t] = s_cscore[t];
        o_clen[b * 8 + t]   = (float)s_clen[t];
    }
    for (int i = t; i < 8 * (NL + 1); i += 512) {
        int j = i / (NL + 1), p = i - j * (NL + 1);
        int v = (p < NL) ? cand_seqs[(b * 8 + s_selpar[j]) * NL + p] : s_selsym[j];
        o_seqs[(b * 8 + j) * (NL + 1) + p] = (float)v;
    }
    for (int i = t; i < 8 * NMAXL; i += 512) {
        int j = i >> 7, p = i & 127;
        int ci = s_cidx[j];
        int v;
        if (ci < 8) v = completed_seqs[(b * 8 + ci) * NMAXL + p];
        else        v = (p < NL) ? cand_seqs[(b * 8 + (ci - 8)) * NL + p] : NEOS;
        o_cseqs[(b * 8 + j) * NMAXL + p] = (float)v;
    }

    // Parent-gather of decoder state (float4 copies), 8 rows per block
    for (int j = 0; j < 8; j++) {
        int row = b * 8 + j;
        int src = b * 8 + s_selpar[j];
        const float4* s = (const float4*)(dctx + (size_t)src * NA);
        float4* d = (float4*)(out + OFF6 + (size_t)row * NA);
        for (int i = t; i < NA / 4; i += 512) d[i] = s[i];
        s = (const float4*)(dr1 + (size_t)src * ND);
        d = (float4*)(out + OFF7 + (size_t)row * ND);
        for (int i = t; i < ND / 4; i += 512) d[i] = s[i];
        s = (const float4*)(dr2 + (size_t)src * ND);
        d = (float4*)(out + OFF8 + (size_t)row * ND);
        for (int i = t; i < ND / 4; i += 512) d[i] = s[i];
    }
}

// ---------------------------------------------------------------------------
extern "C" void kernel_launch(void* const* d_in, const int* in_sizes, int n_in,
                              void* d_out, int out_size) {
    const float* logits            = (const float*)d_in[0];
    const float* cand_scores       = (const float*)d_in[1];
    const int*   cand_seqs         = (const int*)d_in[2];
    const float* completed_scores  = (const float*)d_in[3];
    const int*   completed_seqs    = (const int*)d_in[4];
    const int*   completed_length  = (const int*)d_in[5];
    const float* dctx              = (const float*)d_in[6];
    const float* dr1               = (const float*)d_in[7];
    const float* dr2               = (const float*)d_in[8];
    float* out = (float*)d_out;

    k_rows<<<ROWS, 512>>>(logits, cand_scores);
    k_epilogue<<<NB, 512>>>(cand_seqs, completed_scores, completed_seqs, completed_length,
                            dctx, dr1, dr2, out);
}

// round 6
// speedup vs baseline: 1.3874x; 1.3874x over previous
#include <cuda_runtime.h>
#include <math_constants.h>

// Problem constants
constexpr int NB = 128, NK = 8, NV = 50257, NL = 64, NMAXL = 128, NA = 512, ND = 1024;
constexpr int NEOS = 2;
constexpr int ROWS = NB * NK;   // 1024

// Output layout (single float32 dtype; integer outputs written as floats)
constexpr size_t OFF0 = 0;
constexpr size_t OFF1 = OFF0 + (size_t)NB * NK;
constexpr size_t OFF2 = OFF1 + (size_t)NB * NK * (NL + 1);
constexpr size_t OFF3 = OFF2 + (size_t)NB * NK;
constexpr size_t OFF4 = OFF3 + (size_t)NB * NK;
constexpr size_t OFF5 = OFF4 + (size_t)NB * NK * NMAXL;
constexpr size_t OFF6 = OFF5 + (size_t)NB * NK;
constexpr size_t OFF7 = OFF6 + (size_t)NB * NK * NA;
constexpr size_t OFF8 = OFF7 + (size_t)NB * NK * ND;

// Device scratch
__device__ float g_top_val[ROWS * 8];
__device__ int   g_top_idx[ROWS * 8];
__device__ float g_row_c[ROWS];
__device__ float g_eos[ROWS];

// Packed orderable key: larger == (larger val, then smaller idx). 0 = sentinel.
__device__ __forceinline__ unsigned long long pack_key(float v, unsigned int idx) {
    unsigned int u = __float_as_uint(v);
    u = (u & 0x80000000u) ? ~u : (u | 0x80000000u);
    return ((unsigned long long)u << 32) | (unsigned long long)(0xFFFFFFFFu - idx);
}
__device__ __forceinline__ float key_val(unsigned long long k) {
    unsigned int u = (unsigned int)(k >> 32);
    unsigned int bits = (u & 0x80000000u) ? (u ^ 0x80000000u) : ~u;
    return __uint_as_float(bits);
}
__device__ __forceinline__ unsigned key_low(unsigned long long k) {
    return 0xFFFFFFFFu - (unsigned int)(k & 0xFFFFFFFFu);
}

constexpr int CAP = 2048;

struct RedSmem {
    unsigned long long keys[16];
    unsigned long long win;
};

// Block-wide argmax over packed keys (512 threads). All threads must call.
__device__ __forceinline__ unsigned long long block_argmax(unsigned long long my,
                                                           RedSmem& rs, int tid) {
    int lane = tid & 31, wid = tid >> 5;
    unsigned long long k = my;
#pragma unroll
    for (int off = 16; off; off >>= 1) {
        unsigned long long o = __shfl_xor_sync(0xFFFFFFFFu, k, off);
        if (o > k) k = o;
    }
    if (lane == 0) rs.keys[wid] = k;
    __syncthreads();
    if (tid < 16) {
        unsigned long long kk = rs.keys[tid];
#pragma unroll
        for (int off = 8; off; off >>= 1) {
            unsigned long long o = __shfl_xor_sync(0x0000FFFFu, kk, off);
            if (o > kk) kk = o;
        }
        if (tid == 0) rs.win = kk;
    }
    __syncthreads();
    return rs.win;
}

// ---------------------------------------------------------------------------
// Kernel 1: per (b,k) row — fused sumexp + threshold-filtered top-8
// ---------------------------------------------------------------------------
__global__ __launch_bounds__(512) void k_rows(const float* __restrict__ logits,
                                              const float* __restrict__ cand_scores) {
    const int row = blockIdx.x;
    const int tid = threadIdx.x;
    const float* rl = logits + (long long)row * NV;

    __shared__ unsigned long long s_buf[CAP];
    __shared__ float s_red[512];
    __shared__ RedSmem s_rs;
    __shared__ int s_cnt;
    __shared__ float s_eosv;
    __shared__ float s_tau;

    if (tid == 0) s_cnt = 0;

    // ---- Phase 1: tau from 8192-element sample ----
    // Per-thread max over 16 strided samples (EOS excluded), then tau = 8th
    // largest of the 512 maxima. Guarantees >=8 distinct non-EOS elements
    // with value >= tau, hence tau <= true 8th-largest non-EOS value.
    {
        float m = -CUDART_INF_F;
#pragma unroll
        for (int i = 0; i < 16; ++i) {
            int idx = i * 512 + tid;
            float x = rl[idx];
            if (idx == NEOS) { s_eosv = x; x = -CUDART_INF_F; }
            m = fmaxf(m, x);
        }
        unsigned long long mk = pack_key(m, (unsigned)tid);
        unsigned long long win = 0;
        for (int r = 0; r < 8; ++r) {
            win = block_argmax(mk, s_rs, tid);
            if (mk == win) mk = 0;
        }
        if (tid == 0) s_tau = key_val(win);
        __syncthreads();
    }
    const float tau = s_tau;

    // ---- Phase 2: full scan: sumexp + push candidates (x >= tau) ----
    float sum0 = 0.f, sum1 = 0.f, sum2 = 0.f, sum3 = 0.f;

    // alignment peel (row base is only 4B aligned)
    const int pre = (int)(((16u - ((unsigned)(unsigned long long)rl & 15u)) & 15u) >> 2);
    const int nvec = (NV - pre) >> 2;
    const int F = nvec >> 9;              // full 512-chunks
    const int tstart = pre + nvec * 4;

    if (tid < pre) {
        float x = rl[tid];
        sum0 += __expf(x);
        if (x >= tau) {
            int p = atomicAdd(&s_cnt, 1);
            if (p < CAP) s_buf[p] = pack_key(x, (unsigned)tid);
        }
    }

    const float4* rl4 = (const float4*)(rl + pre);

    // Main loop: 2x unrolled over full chunks; all 512 threads active, so the
    // __any_sync collectives always run on full warps.
    int it = 0;
    for (; it + 2 <= F; it += 2) {
        int v0 = tid + (it << 9);
        int v1 = v0 + 512;
        float4 a = rl4[v0];
        float4 b = rl4[v1];
        sum0 += __expf(a.x); sum1 += __expf(a.y);
        sum2 += __expf(a.z); sum3 += __expf(a.w);
        float ma = fmaxf(fmaxf(a.x, a.y), fmaxf(a.z, a.w));
        if (__any_sync(0xFFFFFFFFu, ma >= tau)) {
            unsigned base = (unsigned)(pre + 4 * v0);
            if (a.x >= tau) { int p = atomicAdd(&s_cnt, 1); if (p < CAP) s_buf[p] = pack_key(a.x, base + 0); }
            if (a.y >= tau) { int p = atomicAdd(&s_cnt, 1); if (p < CAP) s_buf[p] = pack_key(a.y, base + 1); }
            if (a.z >= tau) { int p = atomicAdd(&s_cnt, 1); if (p < CAP) s_buf[p] = pack_key(a.z, base + 2); }
            if (a.w >= tau) { int p = atomicAdd(&s_cnt, 1); if (p < CAP) s_buf[p] = pack_key(a.w, base + 3); }
        }
        sum0 += __expf(b.x); sum1 += __expf(b.y);
        sum2 += __expf(b.z); sum3 += __expf(b.w);
        float mb = fmaxf(fmaxf(b.x, b.y), fmaxf(b.z, b.w));
        if (__any_sync(0xFFFFFFFFu, mb >= tau)) {
            unsigned base = (unsigned)(pre + 4 * v1);
            if (b.x >= tau) { int p = atomicAdd(&s_cnt, 1); if (p < CAP) s_buf[p] = pack_key(b.x, base + 0); }
            if (b.y >= tau) { int p = atomicAdd(&s_cnt, 1); if (p < CAP) s_buf[p] = pack_key(b.y, base + 1); }
            if (b.z >= tau) { int p = atomicAdd(&s_cnt, 1); if (p < CAP) s_buf[p] = pack_key(b.z, base + 2); }
            if (b.w >= tau) { int p = atomicAdd(&s_cnt, 1); if (p < CAP) s_buf[p] = pack_key(b.w, base + 3); }
        }
    }
    if (it < F) {  // odd leftover full chunk (all threads active)
        int v = tid + (it << 9);
        float4 a = rl4[v];
        sum0 += __expf(a.x); sum1 += __expf(a.y);
        sum2 += __expf(a.z); sum3 += __expf(a.w);
        float ma = fmaxf(fmaxf(a.x, a.y), fmaxf(a.z, a.w));
        if (__any_sync(0xFFFFFFFFu, ma >= tau)) {
            unsigned base = (unsigned)(pre + 4 * v);
            if (a.x >= tau) { int p = atomicAdd(&s_cnt, 1); if (p < CAP) s_buf[p] = pack_key(a.x, base + 0); }
            if (a.y >= tau) { int p = atomicAdd(&s_cnt, 1); if (p < CAP) s_buf[p] = pack_key(a.y, base + 1); }
            if (a.z >= tau) { int p = atomicAdd(&s_cnt, 1); if (p < CAP) s_buf[p] = pack_key(a.z, base + 2); }
            if (a.w >= tau) { int p = atomicAdd(&s_cnt, 1); if (p < CAP) s_buf[p] = pack_key(a.w, base + 3); }
        }
    }
    {   // partial vec chunk (no collectives; predicated pushes)
        int v = tid + (F << 9);
        if (v < nvec) {
            float4 a = rl4[v];
            sum0 += __expf(a.x); sum1 += __expf(a.y);
            sum2 += __expf(a.z); sum3 += __expf(a.w);
            unsigned base = (unsigned)(pre + 4 * v);
            if (a.x >= tau) { int p = atomicAdd(&s_cnt, 1); if (p < CAP) s_buf[p] = pack_key(a.x, base + 0); }
            if (a.y >= tau) { int p = atomicAdd(&s_cnt, 1); if (p < CAP) s_buf[p] = pack_key(a.y, base + 1); }
            if (a.z >= tau) { int p = atomicAdd(&s_cnt, 1); if (p < CAP) s_buf[p] = pack_key(a.z, base + 2); }
            if (a.w >= tau) { int p = atomicAdd(&s_cnt, 1); if (p < CAP) s_buf[p] = pack_key(a.w, base + 3); }
        }
    }
    {   // scalar tail (<=3 elements)
        int idx = tstart + tid;
        if (idx < NV) {
            float x = rl[idx];
            sum0 += __expf(x);
            if (x >= tau) {
                int p = atomicAdd(&s_cnt, 1);
                if (p < CAP) s_buf[p] = pack_key(x, (unsigned)idx);
            }
        }
    }

    // ---- Sum reduce -> logZ ----
    s_red[tid] = (sum0 + sum1) + (sum2 + sum3);
    __syncthreads();
#pragma unroll
    for (int s = 256; s > 0; s >>= 1) {
        if (tid < s) s_red[tid] += s_red[tid + s];
        __syncthreads();
    }
    float logZ = logf(s_red[0]);

    if (tid == 0) {
        float cs = cand_scores[row];
        g_row_c[row] = cs - logZ;
        g_eos[row]   = s_eosv - logZ + cs;
    }

    const int cnt = s_cnt;
    if (cnt <= CAP) {
        // remove EOS entry if it slipped in (tau guarantees >=8 non-EOS survivors)
        for (int i = tid; i < cnt; i += 512)
            if (key_low(s_buf[i]) == (unsigned)NEOS) s_buf[i] = 0;
        __syncthreads();
        // ---- Top-8 from candidate buffer: 8 block-argmax rounds ----
        for (int r = 0; r < 8; ++r) {
            unsigned long long my = 0;
            for (int i = tid; i < cnt; i += 512) {
                unsigned long long k = s_buf[i];
                if (k > my) my = k;
            }
            unsigned long long win = block_argmax(my, s_rs, tid);
            if (tid == 0) {
                g_top_val[row * 8 + r] = key_val(win);
                g_top_idx[row * 8 + r] = (int)key_low(win);
            }
            for (int i = tid; i < cnt; i += 512) {
                if (s_buf[i] == win) s_buf[i] = 0;
            }
            __syncthreads();
        }
    } else {
        // ---- Correct fallback (statistically never taken): per-thread sorted top-8 ----
        float tv[8]; int ti[8];
#pragma unroll
        for (int j = 0; j < 8; j++) { tv[j] = -CUDART_INF_F; ti[j] = 0x7FFFFFFF; }
        for (int v = tid; v < NV; v += 512) {
            if (v == NEOS) continue;
            float x = rl[v];
            if ((x > tv[7]) || (x == tv[7] && v < ti[7])) {
                tv[7] = x; ti[7] = v;
#pragma unroll
                for (int j = 7; j >= 1; --j) {
                    bool sw = (tv[j] > tv[j-1]) || (tv[j] == tv[j-1] && ti[j] < ti[j-1]);
                    float av = sw ? tv[j] : tv[j-1];
                    float bv = sw ? tv[j-1] : tv[j];
                    int ai = sw ? ti[j] : ti[j-1];
                    int bi = sw ? ti[j-1] : ti[j];
                    tv[j-1] = av; ti[j-1] = ai; tv[j] = bv; ti[j] = bi;
                }
            }
        }
        for (int r = 0; r < 8; ++r) {
            unsigned long long my = pack_key(tv[0], (unsigned)ti[0]);
            unsigned long long win = block_argmax(my, s_rs, tid);
            if (tid == 0) {
                g_top_val[row * 8 + r] = key_val(win);
                g_top_idx[row * 8 + r] = (int)key_low(win);
            }
            if (my == win) {
#pragma unroll
                for (int j = 0; j < 7; j++) { tv[j] = tv[j+1]; ti[j] = ti[j+1]; }
                tv[7] = -CUDART_INF_F; ti[7] = 0x7FFFFFFF;
            }
            __syncthreads();
        }
    }
}

// ---------------------------------------------------------------------------
// Kernel 2: one block per output row. Warp 0 re-derives the batch selection
// (redundant x8 across the batch's blocks, but fully parallel); warp 1 the
// completed-beam merge. Then the block writes its row's outputs + gathers.
// ---------------------------------------------------------------------------
__global__ __launch_bounds__(256) void k_epilogue(const int* __restrict__ cand_seqs,
                                                  const float* __restrict__ completed_scores,
                                                  const int* __restrict__ completed_seqs,
                                                  const int* __restrict__ completed_length,
                                                  const float* __restrict__ dctx,
                                                  const float* __restrict__ dr1,
                                                  const float* __restrict__ dr2,
                                                  float* __restrict__ out) {
    const int row = blockIdx.x;
    const int b = row >> 3, k = row & 7;
    const int t = threadIdx.x;

    __shared__ float s_selval[8]; __shared__ int s_selpar[8]; __shared__ int s_selsym[8];
    __shared__ float s_cscore[8]; __shared__ int s_clen[8]; __shared__ int s_cidx[8];

    if (t < 32) {
        // top-8 of the batch's 64 candidates via 8 warp-argmax rounds
        int l = t;
        float va = g_top_val[b * 64 + l]       + g_row_c[b * 8 + (l >> 3)];
        float vb = g_top_val[b * 64 + l + 32]  + g_row_c[b * 8 + ((l + 32) >> 3)];
        unsigned fa = (unsigned)((l >> 3) * NV + g_top_idx[b * 64 + l]);
        unsigned fb = (unsigned)(((l + 32) >> 3) * NV + g_top_idx[b * 64 + l + 32]);
        unsigned long long ka = pack_key(va, fa);
        unsigned long long kb = pack_key(vb, fb);
        for (int r = 0; r < 8; ++r) {
            unsigned long long my = (ka > kb) ? ka : kb;
            unsigned long long w = my;
#pragma unroll
            for (int off = 16; off; off >>= 1) {
                unsigned long long o = __shfl_xor_sync(0xFFFFFFFFu, w, off);
                if (o > w) w = o;
            }
            if (ka == w) ka = 0;
            if (kb == w) kb = 0;
            if (l == 0) {
                unsigned f = key_low(w);
                int par = (int)(f / (unsigned)NV);
                s_selval[r] = key_val(w);
                s_selpar[r] = par;
                s_selsym[r] = (int)(f - (unsigned)par * (unsigned)NV);
            }
        }
    } else if (t < 64) {
        // completed-beam merge: 16 candidates ranked by score/len (stable)
        int l = t - 32;
        float cs = 0.f; int cl = 1;
        unsigned long long key = 0;
        if (l < 16) {
            cs = (l < 8) ? completed_scores[b * 8 + l] : g_eos[b * 8 + (l - 8)];
            cl = (l < 8) ? completed_length[b * 8 + l] : (NL + 1);
            key = pack_key(cs / (float)cl, (unsigned)l);
        }
        for (int r = 0; r < 8; ++r) {
            unsigned long long w = key;
#pragma unroll
            for (int off = 16; off; off >>= 1) {
                unsigned long long o = __shfl_xor_sync(0xFFFFFFFFu, w, off);
                if (o > w) w = o;
            }
            if (key == w && key != 0) {
                s_cidx[r] = l; s_cscore[r] = cs; s_clen[r] = cl;
                key = 0;
            }
        }
    }
    __syncthreads();

    float* o_scores = out + OFF0;
    float* o_seqs   = out + OFF1;
    float* o_par    = out + OFF2;
    float* o_cscore = out + OFF3;
    float* o_cseqs  = out + OFF4;
    float* o_clen   = out + OFF5;

    const int par = s_selpar[k];
    const int ci  = s_cidx[k];

    if (t == 0) {
        o_scores[row] = s_selval[k];
        o_par[row]    = (float)par;
        o_cscore[row] = s_cscore[k];
        o_clen[row]   = (float)s_clen[k];
    }
    // new_seqs row (65 values)
    if (t < NL + 1) {
        int v = (t < NL) ? cand_seqs[(b * 8 + par) * NL + t] : s_selsym[k];
        o_seqs[row * (NL + 1) + t] = (float)v;
    }
    // comp_seqs row (128 values)
    if (t < NMAXL) {
        int v;
        if (ci < 8) v = completed_seqs[(b * 8 + ci) * NMAXL + t];
        else        v = (t < NL) ? cand_seqs[(b * 8 + (ci - 8)) * NL + t] : NEOS;
        o_cseqs[row * NMAXL + t] = (float)v;
    }

    // Parent-gather of decoder state (float4 copies)
    const int src = b * 8 + par;
    {
        const float4* s = (const float4*)(dctx + (size_t)src * NA);
        float4* d = (float4*)(out + OFF6 + (size_t)row * NA);
#pragma unroll
        for (int i = t; i < NA / 4; i += 256) d[i] = s[i];
    }
    {
        const float4* s = (const float4*)(dr1 + (size_t)src * ND);
        float4* d = (float4*)(out + OFF7 + (size_t)row * ND);
#pragma unroll
        for (int i = t; i < ND / 4; i += 256) d[i] = s[i];
    }
    {
        const float4* s = (const float4*)(dr2 + (size_t)src * ND);
        float4* d = (float4*)(out + OFF8 + (size_t)row * ND);
#pragma unroll
        for (int i = t; i < ND / 4; i += 256) d[i] = s[i];
    }
}

// ---------------------------------------------------------------------------
extern "C" void kernel_launch(void* const* d_in, const int* in_sizes, int n_in,
                              void* d_out, int out_size) {
    const float* logits            = (const float*)d_in[0];
    const float* cand_scores       = (const float*)d_in[1];
    const int*   cand_seqs         = (const int*)d_in[2];
    const float* completed_scores  = (const float*)d_in[3];
    const int*   completed_seqs    = (const int*)d_in[4];
    const int*   completed_length  = (const int*)d_in[5];
    const float* dctx              = (const float*)d_in[6];
    const float* dr1               = (const float*)d_in[7];
    const float* dr2               = (const float*)d_in[8];
    float* out = (float*)d_out;

    k_rows<<<ROWS, 512>>>(logits, cand_scores);
    k_epilogue<<<ROWS, 256>>>(cand_seqs, completed_scores, completed_seqs, completed_length,
                              dctx, dr1, dr2, out);
}